// round 16
// baseline (speedup 1.0000x reference)
#include <cuda_runtime.h>
#include <cuda_bf16.h>
#include <cstdint>

#define CC      2048
#define HW      49
#define SIDE    7
#define NTHR    512
#define SPLIT   16
#define CHC     (CC / SPLIT)      // 128 channels per CTA
#define NGRP    16                // channel groups (one warp each)
#define CPT     (CHC / NGRP)      // 8 channels per thread
#define NMAX    256

// scratch: [u][p][5] = {sum, a0, a1, d0, d1}
__device__ float g_scratch[NMAX * SPLIT * HW * 5];

#define FMA2(acc, v, w) asm("fma.rn.f32x2 %0, %1, %2, %0;" : "+l"(acc) : "l"(v), "l"(w))
#define ADD2(acc, v)    asm("add.rn.f32x2 %0, %1, %0;"     : "+l"(acc) : "l"(v))

__device__ __forceinline__ uint64_t pack2(float a, float b) {
    uint64_t r;
    asm("mov.b64 %0, {%1, %2};" : "=l"(r) : "f"(a), "f"(b));
    return r;
}
__device__ __forceinline__ void unpack2(uint64_t r, float& a, float& b) {
    asm("mov.b64 {%0, %1}, %2;" : "=f"(a), "=f"(b) : "l"(r));
}

// ------- K1: streaming partial, 5 packed f32x2 accs over position pairs -------
__global__ __launch_bounds__(NTHR, 3)
void rpcp_partial_kernel(const float* __restrict__ x,
                         const float* __restrict__ Wlin,
                         float* __restrict__ scratch)
{
    // pre-splatted weights: wA[c] = {{W1_0,W1_0},{W1_1,W1_1}}, wD[c] = {{W2_0,W2_0},{W2_1,W2_1}}
    __shared__ alignas(16) ulonglong2 wA[CHC];   // 2 KB
    __shared__ alignas(16) ulonglong2 wD[CHC];   // 2 KB
    __shared__ float acc[NGRP][HW][5];           // 15.7 KB

    const int tid = threadIdx.x;
    const int u   = blockIdx.x;               // unit id
    const int n   = u >> 4;                   // SPLIT = 16
    const int sp  = u & 15;
    const int c0  = sp * CHC;

    for (int c = tid; c < CHC; c += NTHR) {
        const int cc = c0 + c;
        const uint32_t w10 = __float_as_uint(Wlin[cc]);
        const uint32_t w11 = __float_as_uint(Wlin[2 * CC + cc]);
        const uint32_t w20 = __float_as_uint(Wlin[CC + cc]);
        const uint32_t w21 = __float_as_uint(Wlin[3 * CC + cc]);
        wA[c] = make_ulonglong2(((uint64_t)w10 << 32) | w10,
                                ((uint64_t)w11 << 32) | w11);
        wD[c] = make_ulonglong2(((uint64_t)w20 << 32) | w20,
                                ((uint64_t)w21 << 32) | w21);
    }
    __syncthreads();

    const int l  = tid & 31;     // lane
    const int cg = tid >> 5;     // 0..15 (warp-uniform channel group)
    const int p0 = 2 * l;        // positions p0, p0+1

    if (p0 < HW) {
        const int p1 = (p0 + 1 < HW) ? p0 + 1 : p0;   // clamp (lane 24 duplicates)

        uint64_t sP = 0, aP0 = 0, aP1 = 0, dP0 = 0, dP1 = 0;
        const float* xb = x + (size_t)n * CC * HW + (size_t)c0 * HW;
        const float* x0 = xb + p0;
        const float* x1 = xb + p1;

        // 2 rounds x 4 channels: 8 front-batched LDGs, then packed compute
        #pragma unroll
        for (int k = 0; k < 2; k++) {
            float v[8];
            #pragma unroll
            for (int j = 0; j < 4; j++) {
                const int c = cg + (k * 4 + j) * NGRP;
                v[2 * j]     = __ldg(x0 + c * HW);
                v[2 * j + 1] = __ldg(x1 + c * HW);
            }
            #pragma unroll
            for (int j = 0; j < 4; j++) {
                const int c = cg + (k * 4 + j) * NGRP;
                const uint64_t  vv = pack2(v[2 * j], v[2 * j + 1]);   // {v(p0),v(p1)} as hi|lo
                const ulonglong2 a = wA[c];                           // LDS.128 broadcast
                const ulonglong2 d = wD[c];                           // LDS.128 broadcast
                ADD2(sP, vv);
                FMA2(aP0, vv, a.x);
                FMA2(aP1, vv, a.y);
                FMA2(dP0, vv, d.x);
                FMA2(dP1, vv, d.y);
            }
        }

        // unpack: lo half = p0 (first operand of mov.b64 {lo,hi})
        float f0, f1;
        unpack2(sP,  f0, f1); acc[cg][p0][0] = f0; acc[cg][p1][0] = f1;
        unpack2(aP0, f0, f1); acc[cg][p0][1] = f0; acc[cg][p1][1] = f1;
        unpack2(aP1, f0, f1); acc[cg][p0][2] = f0; acc[cg][p1][2] = f1;
        unpack2(dP0, f0, f1); acc[cg][p0][3] = f0; acc[cg][p1][3] = f1;
        unpack2(dP1, f0, f1); acc[cg][p0][4] = f0; acc[cg][p1][4] = f1;
    }
    __syncthreads();

    if (tid < HW * 5) {
        const int pp = tid / 5, k = tid % 5;
        float t = 0.f;
        #pragma unroll
        for (int g = 0; g < NGRP; g++) t += acc[g][pp][k];
        scratch[(u * HW + pp) * 5 + k] = t;
    }
}

// ------- K2: per-image reduce + epilogue (scratch-only, proven) -------
__global__ __launch_bounds__(256, 4)
void rpcp_final_kernel(const float* __restrict__ scratch,
                       const float* __restrict__ bias,
                       float* __restrict__ out)
{
    __shared__ float fin[HW][5];   // {sum, a0, a1, d0, d1}
    __shared__ float gaps[HW];
    __shared__ float dls[HW];
    __shared__ float s_gmean;
    __shared__ int   s_idx;

    const int n   = blockIdx.x;
    const int tid = threadIdx.x;

    if (tid < HW * 5) {
        const int pp = tid / 5, k = tid % 5;
        float t = 0.f;
        #pragma unroll
        for (int g = 0; g < SPLIT; g++)
            t += scratch[(((n << 4) + g) * HW + pp) * 5 + k];
        fin[pp][k] = t;
    }
    __syncthreads();

    // warp argmax over channel-sum (first occurrence on ties)
    if (tid < 32) {
        float v  = fin[tid][0];
        int   bi = tid;
        if (tid + 32 < HW) {
            float v2 = fin[tid + 32][0];
            if (v2 > v) { v = v2; bi = tid + 32; }
        }
        #pragma unroll
        for (int off = 16; off > 0; off >>= 1) {
            float ov = __shfl_down_sync(0xffffffffu, v,  off);
            int   oi = __shfl_down_sync(0xffffffffu, bi, off);
            if (ov > v || (ov == v && oi < bi)) { v = ov; bi = oi; }
        }
        if (tid == 0) s_idx = bi;
    }
    __syncthreads();
    const int idx = s_idx;

    if (tid < HW) {
        const float A0 = fin[idx][1];
        const float A1 = fin[idx][2];
        float pr0 = fin[tid][3] + A0 + __ldg(bias + 0);
        float pr1 = fin[tid][4] + A1 + __ldg(bias + 1);
        pr0 = fmaxf(pr0, 0.f);
        pr1 = fmaxf(pr1, 0.f);
        if (tid == idx) { pr0 = 0.f; pr1 = 0.f; }

        const float ri = (float)(tid / SIDE - idx / SIDE) * (1.f / (float)SIDE);
        const float rj = (float)(tid % SIDE - idx % SIDE) * (1.f / (float)SIDE);
        const float rd = sqrtf(ri * ri + rj * rj);
        const float ang = (atan2f(rj, ri) * (1.f / 3.14159265358979323846f) + 1.f) * 0.5f;

        float dl = pr0 - rd; dl *= dl;
        float g  = pr1 - ang;
        if (g < 0.f) g += 1.f;
        gaps[tid] = g;
        dls[tid]  = dl;
    }
    __syncthreads();

    if (tid < 32) {
        float t = (tid < HW) ? gaps[tid] : 0.f;
        if (tid + 32 < HW) t += gaps[tid + 32];
        #pragma unroll
        for (int off = 16; off > 0; off >>= 1)
            t += __shfl_down_sync(0xffffffffu, t, off);
        if (tid == 0) s_gmean = t * (1.f / (float)HW);
    }
    __syncthreads();

    if (tid < HW) {
        float g = gaps[tid] - s_gmean;
        out[n * HW + tid] = dls[tid] + g * g;
    }
}

extern "C" void kernel_launch(void* const* d_in, const int* in_sizes, int n_in,
                              void* d_out, int out_size)
{
    const float* x    = (const float*)d_in[0];
    const float* Wlin = (const float*)d_in[1];
    const float* b    = (const float*)d_in[2];
    float*       out  = (float*)d_out;

    const int N = in_sizes[0] / (CC * HW);   // 256

    float* scratch = nullptr;
    cudaGetSymbolAddress((void**)&scratch, g_scratch);

    rpcp_partial_kernel<<<N * SPLIT, NTHR>>>(x, Wlin, scratch);
    rpcp_final_kernel<<<N, 256>>>(scratch, b, out);
}

// round 17
// speedup vs baseline: 1.2784x; 1.2784x over previous
#include <cuda_runtime.h>
#include <cuda_bf16.h>
#include <cstdint>

#define CC      2048
#define HW      49
#define SIDE    7
#define CGROUPS 8
#define NTHR    392               // 8 * 49: every thread owns one (cg, p)
#define SPLIT   16
#define CHC     (CC / SPLIT)      // 128 channels per CTA
#define NMAX    256

// scratch: [u][p][5] = {sum, a0, a1, d0, d1}
__device__ float g_scratch[NMAX * SPLIT * HW * 5];

// ------- K1: streaming partial, dense linear mapping, 5 accs, occ-3 -------
__global__ __launch_bounds__(NTHR, 3)
void rpcp_partial_kernel(const float* __restrict__ x,
                         const float* __restrict__ Wlin,
                         float* __restrict__ scratch)
{
    __shared__ float4 wsh[CHC];               // {W1_0, W1_1, W2_0, W2_1}: 2 KB
    __shared__ float  acc[CGROUPS][HW][5];

    const int tid = threadIdx.x;
    const int u   = blockIdx.x;               // unit id
    const int n   = u >> 4;                   // SPLIT = 16
    const int sp  = u & 15;
    const int c0  = sp * CHC;

    for (int c = tid; c < CHC; c += NTHR) {
        const int cc = c0 + c;
        wsh[c] = make_float4(Wlin[cc],             // W1_0
                             Wlin[2 * CC + cc],    // W1_1
                             Wlin[CC + cc],        // W2_0
                             Wlin[3 * CC + cc]);   // W2_1
    }
    __syncthreads();

    const int cg = tid / HW;     // 0..7  (2 values per warp)
    const int p  = tid % HW;     // 0..48

    // element (cg + j*8, p) lives at slice_base + tid + j*392  — dense!
    {
        float s = 0.f, a0 = 0.f, a1 = 0.f, d0 = 0.f, d1 = 0.f;
        const float* xp = x + (size_t)n * CC * HW + (size_t)c0 * HW + tid;

        #pragma unroll
        for (int k = 0; k < 2; k++) {
            float v[8];
            #pragma unroll
            for (int j = 0; j < 8; j++)
                v[j] = __ldg(xp + (k * 8 + j) * NTHR);   // 128B-dense per warp

            #pragma unroll
            for (int j = 0; j < 8; j++) {
                const float4 w = wsh[cg + (k * 8 + j) * CGROUPS];
                s  += v[j];
                a0 = fmaf(v[j], w.x, a0);
                a1 = fmaf(v[j], w.y, a1);
                d0 = fmaf(v[j], w.z, d0);
                d1 = fmaf(v[j], w.w, d1);
            }
        }

        acc[cg][p][0] = s;  acc[cg][p][1] = a0; acc[cg][p][2] = a1;
        acc[cg][p][3] = d0; acc[cg][p][4] = d1;
    }
    __syncthreads();

    if (tid < HW * 5) {
        const int pp = tid / 5, k = tid % 5;
        float t = 0.f;
        #pragma unroll
        for (int g = 0; g < CGROUPS; g++) t += acc[g][pp][k];
        scratch[(u * HW + pp) * 5 + k] = t;
    }
}

// ------- K2: per-image reduce + epilogue (scratch-only, proven) -------
__global__ __launch_bounds__(256, 4)
void rpcp_final_kernel(const float* __restrict__ scratch,
                       const float* __restrict__ bias,
                       float* __restrict__ out)
{
    __shared__ float fin[HW][5];   // {sum, a0, a1, d0, d1}
    __shared__ float gaps[HW];
    __shared__ float dls[HW];
    __shared__ float s_gmean;
    __shared__ int   s_idx;

    const int n   = blockIdx.x;
    const int tid = threadIdx.x;

    if (tid < HW * 5) {
        const int pp = tid / 5, k = tid % 5;
        float t = 0.f;
        #pragma unroll
        for (int g = 0; g < SPLIT; g++)
            t += scratch[(((n << 4) + g) * HW + pp) * 5 + k];
        fin[pp][k] = t;
    }
    __syncthreads();

    // warp argmax over channel-sum (first occurrence on ties)
    if (tid < 32) {
        float v  = fin[tid][0];
        int   bi = tid;
        if (tid + 32 < HW) {
            float v2 = fin[tid + 32][0];
            if (v2 > v) { v = v2; bi = tid + 32; }
        }
        #pragma unroll
        for (int off = 16; off > 0; off >>= 1) {
            float ov = __shfl_down_sync(0xffffffffu, v,  off);
            int   oi = __shfl_down_sync(0xffffffffu, bi, off);
            if (ov > v || (ov == v && oi < bi)) { v = ov; bi = oi; }
        }
        if (tid == 0) s_idx = bi;
    }
    __syncthreads();
    const int idx = s_idx;

    if (tid < HW) {
        const float A0 = fin[idx][1];
        const float A1 = fin[idx][2];
        float pr0 = fin[tid][3] + A0 + __ldg(bias + 0);
        float pr1 = fin[tid][4] + A1 + __ldg(bias + 1);
        pr0 = fmaxf(pr0, 0.f);
        pr1 = fmaxf(pr1, 0.f);
        if (tid == idx) { pr0 = 0.f; pr1 = 0.f; }

        const float ri = (float)(tid / SIDE - idx / SIDE) * (1.f / (float)SIDE);
        const float rj = (float)(tid % SIDE - idx % SIDE) * (1.f / (float)SIDE);
        const float rd = sqrtf(ri * ri + rj * rj);
        const float ang = (atan2f(rj, ri) * (1.f / 3.14159265358979323846f) + 1.f) * 0.5f;

        float dl = pr0 - rd; dl *= dl;
        float g  = pr1 - ang;
        if (g < 0.f) g += 1.f;
        gaps[tid] = g;
        dls[tid]  = dl;
    }
    __syncthreads();

    if (tid < 32) {
        float t = (tid < HW) ? gaps[tid] : 0.f;
        if (tid + 32 < HW) t += gaps[tid + 32];
        #pragma unroll
        for (int off = 16; off > 0; off >>= 1)
            t += __shfl_down_sync(0xffffffffu, t, off);
        if (tid == 0) s_gmean = t * (1.f / (float)HW);
    }
    __syncthreads();

    if (tid < HW) {
        float g = gaps[tid] - s_gmean;
        out[n * HW + tid] = dls[tid] + g * g;
    }
}

extern "C" void kernel_launch(void* const* d_in, const int* in_sizes, int n_in,
                              void* d_out, int out_size)
{
    const float* x    = (const float*)d_in[0];
    const float* Wlin = (const float*)d_in[1];
    const float* b    = (const float*)d_in[2];
    float*       out  = (float*)d_out;

    const int N = in_sizes[0] / (CC * HW);   // 256

    float* scratch = nullptr;
    cudaGetSymbolAddress((void**)&scratch, g_scratch);

    rpcp_partial_kernel<<<N * SPLIT, NTHR>>>(x, Wlin, scratch);
    rpcp_final_kernel<<<N, 256>>>(scratch, b, out);
}